// round 8
// baseline (speedup 1.0000x reference)
#include <cuda_runtime.h>
#include <cstdint>

#define NN    100000
#define EMAX  3200000
#define CAP   128            // max slots per node (P(overflow) ~ 1e-44)
#define FULL  0xffffffffu

// ---------------- scratch (device globals) ----------------------------------
__device__ float g_out1[NN * 16];    // layer1 output (post relu)
__device__ float g_ad  [NN];         // alpha_dst (layer1, then layer2)
__device__ float g_w1a [4];          // W1@a_src1 (2), W1@a_dst1 (2)
__device__ float g_w2a [32];         // W2@a_src2 (16), W2@a_dst2 (16)
__device__ int   g_cnt [NN];         // per-node slot counter (self-cleaned by agg2)
__device__ int   g_srcl[NN * CAP];   // fixed-stride adjacency rows (51.2 MB)

__device__ __forceinline__ float lrelu(float v) { return v > 0.f ? v : 0.2f * v; }

__device__ __forceinline__ void put_edge(int dst, int src) {
    int p = atomicAdd(&g_cnt[dst], 1);
    if (p < CAP) g_srcl[dst * CAP + p] = src;
}

// ---------------- fused build: hist+scatter (8 edges/thread) + node init ----
// g_cnt must be zero on entry (zero at load; reset by k_agg2 each call).
__global__ void k_build(const int* __restrict__ ei, const float* __restrict__ x,
                        const float* __restrict__ W1, const float* __restrict__ as1,
                        const float* __restrict__ ad1,
                        const float* __restrict__ W2, const float* __restrict__ as2,
                        const float* __restrict__ ad2,
                        int E, int n) {
    int t  = blockIdx.x * blockDim.x + threadIdx.x;
    int E8 = E >> 3;
    if (t < E8) {
        int4 s0 = ((const int4*)ei)[2 * t];
        int4 s1 = ((const int4*)ei)[2 * t + 1];
        int4 d0 = ((const int4*)(ei + E))[2 * t];
        int4 d1 = ((const int4*)(ei + E))[2 * t + 1];
        put_edge(d0.x, s0.x); put_edge(d0.y, s0.y);
        put_edge(d0.z, s0.z); put_edge(d0.w, s0.w);
        put_edge(d1.x, s1.x); put_edge(d1.y, s1.y);
        put_edge(d1.z, s1.z); put_edge(d1.w, s1.w);
    } else if (t == E8) {
        for (int e = E8 * 8; e < E; e++) put_edge(ei[E + e], ei[e]);
    }
    if (t < n) {
        put_edge(t, t);                      // self loop as a normal slot
        // local projection of a_dst1 through W1 (W1 is [2][16])
        float d0 = 0.f, d1 = 0.f;
        #pragma unroll
        for (int f = 0; f < 16; f++) {
            float a = __ldg(ad1 + f);
            d0 += __ldg(W1 + f) * a;
            d1 += __ldg(W1 + 16 + f) * a;
        }
        float2 xv = ((const float2*)x)[t];
        g_ad[t] = xv.x * d0 + xv.y * d1;
    }
    if (t < 2) {   // g_w1a
        float s = 0.f, d = 0.f;
        #pragma unroll
        for (int f = 0; f < 16; f++) {
            s += __ldg(W1 + t * 16 + f) * __ldg(as1 + f);
            d += __ldg(W1 + t * 16 + f) * __ldg(ad1 + f);
        }
        g_w1a[t] = s; g_w1a[2 + t] = d;
    }
    if (t < 16) {  // g_w2a
        float s = 0.f, d = 0.f;
        #pragma unroll
        for (int f = 0; f < 64; f++) {
            s += __ldg(W2 + t * 64 + f) * __ldg(as2 + f);
            d += __ldg(W2 + t * 64 + f) * __ldg(ad2 + f);
        }
        g_w2a[t] = s; g_w2a[16 + t] = d;
    }
}

// ---------------- layer1 aggregate: warp/dst, 1 lane/edge, linearity trick --
__global__ void k_agg1_csr(const float* __restrict__ x, const float* __restrict__ W1,
                           const float* __restrict__ b1, int n) {
    int warp = (blockIdx.x * blockDim.x + threadIdx.x) >> 5;
    if (warp >= n) return;
    int lane = threadIdx.x & 31;
    int deg  = g_cnt[warp]; deg = deg < CAP ? deg : CAP;
    const int* row = g_srcl + warp * CAP;
    float adv = g_ad[warp];
    float wa0 = g_w1a[0], wa1 = g_w1a[1];
    float psum = 0.f, px0 = 0.f, px1 = 0.f;
    for (int i = lane; i < deg; i += 32) {
        int src = row[i];
        float2 xv = ((const float2*)x)[src];
        float p = __expf(lrelu(xv.x * wa0 + xv.y * wa1 + adv));
        psum += p; px0 += p * xv.x; px1 += p * xv.y;
    }
    #pragma unroll
    for (int o = 16; o >= 1; o >>= 1) {       // post-loop: warp fully convergent
        psum += __shfl_xor_sync(FULL, psum, o);
        px0  += __shfl_xor_sync(FULL, px0,  o);
        px1  += __shfl_xor_sync(FULL, px1,  o);
    }
    if (lane < 16) {
        float sinv = 1.f / psum;
        float v = fmaxf((px0 * __ldg(W1 + lane) + px1 * __ldg(W1 + 16 + lane)) * sinv
                        + __ldg(b1 + lane), 0.f);
        g_out1[warp * 16 + lane] = v;
        float pd = v * g_w2a[16 + lane];      // alpha_dst for layer 2
        #pragma unroll
        for (int o = 8; o >= 1; o >>= 1)
            pd += __shfl_xor_sync(0xffffu, pd, o);
        if (lane == 0) g_ad[warp] = pd;
    }
}

// ---------------- layer2 aggregate: warp/dst, 4 lanes/edge, pipelined -------
__global__ void k_agg2_csr(const float* __restrict__ W2, const float* __restrict__ b2,
                           float* __restrict__ out, int n) {
    __shared__ float sW[1024];   // W2 16x64
    for (int i = threadIdx.x; i < 1024; i += blockDim.x) sW[i] = W2[i];
    __syncthreads();

    int warp = (blockIdx.x * blockDim.x + threadIdx.x) >> 5;
    if (warp >= n) return;
    int lane = threadIdx.x & 31;
    int fl   = lane & 3;             // feature slice (4 floats)
    int sub  = lane >> 2;            // 8 edges in parallel
    int deg  = g_cnt[warp]; deg = deg < CAP ? deg : CAP;
    if (lane == 0) g_cnt[warp] = 0;  // self-clean for next graph replay
    const int* rowp = g_srcl + warp * CAP;
    float adv = g_ad[warp];
    float wsa = g_w2a[fl * 4 + 0], wsb = g_w2a[fl * 4 + 1];
    float wsc = g_w2a[fl * 4 + 2], wsd = g_w2a[fl * 4 + 3];

    float4 acc = make_float4(0.f, 0.f, 0.f, 0.f);
    float psum = 0.f;
    int iters = (deg + 7) >> 3;                // warp-uniform trip count

    bool  v0 = (sub < deg);
    int   s0 = v0 ? rowp[sub] : 0;
    float4 hv0 = v0 ? *(const float4*)(g_out1 + s0 * 16 + fl * 4)
                    : make_float4(0.f, 0.f, 0.f, 0.f);

    for (int it = 0; it < iters; it++) {
        int i1 = (it + 1) * 8 + sub;
        bool v1 = (i1 < deg);
        int  s1 = v1 ? rowp[i1] : 0;
        float4 hv1 = v1 ? *(const float4*)(g_out1 + s1 * 16 + fl * 4)
                        : make_float4(0.f, 0.f, 0.f, 0.f);

        float pa = hv0.x * wsa + hv0.y * wsb + hv0.z * wsc + hv0.w * wsd;
        pa += __shfl_xor_sync(FULL, pa, 1);
        pa += __shfl_xor_sync(FULL, pa, 2);    // alpha_src, same in all 4 lanes
        float p = v0 ? __expf(lrelu(pa + adv)) : 0.f;
        psum += p;
        acc.x += p * hv0.x; acc.y += p * hv0.y;
        acc.z += p * hv0.z; acc.w += p * hv0.w;

        hv0 = hv1; v0 = v1;
    }
    #pragma unroll
    for (int o = 4; o <= 16; o <<= 1) {        // reduce across the 8 subgroups
        acc.x += __shfl_xor_sync(FULL, acc.x, o);
        acc.y += __shfl_xor_sync(FULL, acc.y, o);
        acc.z += __shfl_xor_sync(FULL, acc.z, o);
        acc.w += __shfl_xor_sync(FULL, acc.w, o);
        psum  += __shfl_xor_sync(FULL, psum,  o);
    }
    float sinv = 1.f / psum;
    float t[16];
    #pragma unroll
    for (int k = 0; k < 16; k++) {
        float c = ((k & 3) == 0) ? acc.x : ((k & 3) == 1) ? acc.y
                 : ((k & 3) == 2) ? acc.z : acc.w;
        t[k] = __shfl_sync(FULL, c, k >> 2) * sinv;   // lane (k>>2) has fl==k>>2
    }
    float2 r = make_float2(0.f, 0.f);
    #pragma unroll
    for (int k = 0; k < 16; k++) {
        float2 w = *(const float2*)&sW[k * 64 + 2 * lane];
        r.x += t[k] * w.x;
        r.y += t[k] * w.y;
    }
    float2 bb = __ldg((const float2*)b2 + lane);
    r.x = fmaxf(r.x + bb.x, 0.f);
    r.y = fmaxf(r.y + bb.y, 0.f);
    ((float2*)(out + warp * 64))[lane] = r;
}

// ---------------- launch -----------------------------------------------------
extern "C" void kernel_launch(void* const* d_in, const int* in_sizes, int n_in,
                              void* d_out, int out_size) {
    const float* x   = (const float*)d_in[0];
    const int*   ei  = (const int*)  d_in[1];
    const float* W1  = (const float*)d_in[2];
    const float* as1 = (const float*)d_in[3];
    const float* ad1 = (const float*)d_in[4];
    const float* b1  = (const float*)d_in[5];
    const float* W2  = (const float*)d_in[6];
    const float* as2 = (const float*)d_in[7];
    const float* ad2 = (const float*)d_in[8];
    const float* b2  = (const float*)d_in[9];
    float* out = (float*)d_out;

    int n  = in_sizes[0] / 2;   // 100000
    int E  = in_sizes[1] / 2;   // 3.2M

    const int T = 256;
    int E8c  = (E >> 3) + 1;                     // 8-edge threads (+tail thread)
    int bthr = E8c > n ? E8c : n;                // build kernel threads

    k_build<<<(bthr + T - 1) / T, T>>>(ei, x, W1, as1, ad1, W2, as2, ad2, E, n);
    k_agg1_csr<<<(n * 32 + T - 1) / T, T>>>(x, W1, b1, n);
    k_agg2_csr<<<(n * 32 + T - 1) / T, T>>>(W2, b2, out, n);
}

// round 9
// speedup vs baseline: 1.7353x; 1.7353x over previous
#include <cuda_runtime.h>
#include <cstdint>

#define NN    100000
#define EMAX  3200000
#define EEMAX (EMAX + NN)
#define FULL  0xffffffffu

// ---------------- scratch (device globals) ----------------------------------
__device__ float g_out1[NN * 16];   // layer1 output (post relu)
__device__ float g_ad  [NN];        // alpha_dst (layer1 then layer2, per node)
__device__ float g_w1a [4];         // W1@a_src1 (2), W1@a_dst1 (2)
__device__ float g_w2a [32];        // W2@a_src2 (16), W2@a_dst2 (16)
// CSR
__device__ int   g_deg [NN];        // transient counts (self-cleaned by scan1)
__device__ int   g_off [NN + 1];    // segment starts; g_off[n] = E+n
__device__ int   g_rank[EMAX];      // per-edge rank within dst segment
__device__ int   g_srcl[EEMAX];     // CSR adjacency (slot0 of each seg = self loop)
__device__ int   g_bsum[128];

__device__ __forceinline__ float lrelu(float v) { return v > 0.f ? v : 0.2f * v; }

__device__ __forceinline__ int4 ldcs4(const int4* p) {
    int4 v;
    asm volatile("ld.global.cs.v4.s32 {%0,%1,%2,%3}, [%4];"
                 : "=r"(v.x), "=r"(v.y), "=r"(v.z), "=r"(v.w) : "l"(p));
    return v;
}
__device__ __forceinline__ void stcs4(int4* p, int4 v) {
    asm volatile("st.global.cs.v4.s32 [%0], {%1,%2,%3,%4};"
                 :: "l"(p), "r"(v.x), "r"(v.y), "r"(v.z), "r"(v.w) : "memory");
}

// ---------------- fused: hist+rank (8 edges/thread) + node init + w1a/w2a ---
// g_deg must be zero on entry (zeroed at load; re-zeroed by k_scan1 each call).
__global__ void k_hist_init(const int* __restrict__ ei, const float* __restrict__ x,
                            const float* __restrict__ W1, const float* __restrict__ as1,
                            const float* __restrict__ ad1,
                            const float* __restrict__ W2, const float* __restrict__ as2,
                            const float* __restrict__ ad2,
                            int E, int n) {
    int t  = blockIdx.x * blockDim.x + threadIdx.x;
    int E8 = E >> 3;
    const int* dsts = ei + E;
    if (t < E8) {
        int4 d0 = ldcs4(((const int4*)dsts) + 2 * t);
        int4 d1 = ldcs4(((const int4*)dsts) + 2 * t + 1);
        int4 r0, r1;
        r0.x = atomicAdd(&g_deg[d0.x], 1);
        r0.y = atomicAdd(&g_deg[d0.y], 1);
        r0.z = atomicAdd(&g_deg[d0.z], 1);
        r0.w = atomicAdd(&g_deg[d0.w], 1);
        r1.x = atomicAdd(&g_deg[d1.x], 1);
        r1.y = atomicAdd(&g_deg[d1.y], 1);
        r1.z = atomicAdd(&g_deg[d1.z], 1);
        r1.w = atomicAdd(&g_deg[d1.w], 1);
        stcs4(((int4*)g_rank) + 2 * t,     r0);
        stcs4(((int4*)g_rank) + 2 * t + 1, r1);
    } else if (t == E8) {
        for (int e = E8 * 8; e < E; e++)
            g_rank[e] = atomicAdd(&g_deg[dsts[e]], 1);
    }
    if (t < n) {
        // local projection of a_dst1 through W1 (W1 is [2][16])
        float d0 = 0.f, d1 = 0.f;
        #pragma unroll
        for (int f = 0; f < 16; f++) {
            float a = __ldg(ad1 + f);
            d0 += __ldg(W1 + f) * a;
            d1 += __ldg(W1 + 16 + f) * a;
        }
        float2 xv = ((const float2*)x)[t];
        g_ad[t] = xv.x * d0 + xv.y * d1;
    }
    if (t < 2) {   // g_w1a
        float s = 0.f, d = 0.f;
        #pragma unroll
        for (int f = 0; f < 16; f++) {
            s += __ldg(W1 + t * 16 + f) * __ldg(as1 + f);
            d += __ldg(W1 + t * 16 + f) * __ldg(ad1 + f);
        }
        g_w1a[t] = s; g_w1a[2 + t] = d;
    }
    if (t < 16) {  // g_w2a
        float s = 0.f, d = 0.f;
        #pragma unroll
        for (int f = 0; f < 64; f++) {
            s += __ldg(W2 + t * 64 + f) * __ldg(as2 + f);
            d += __ldg(W2 + t * 64 + f) * __ldg(ad2 + f);
        }
        g_w2a[t] = s; g_w2a[16 + t] = d;
    }
}

// ---------------- scan phase 1: per-1024 block scan of (deg+1) --------------
#define SCAN_BLK 1024
__global__ void k_scan1(int n) {
    __shared__ int wsum[32];
    int i = blockIdx.x * SCAN_BLK + threadIdx.x;
    int lane = threadIdx.x & 31, w = threadIdx.x >> 5;
    int v = 0;
    if (i < n) {
        v = g_deg[i] + 1;      // +1 = self loop slot
        g_deg[i] = 0;          // self-clean for next graph replay
    }
    int s = v;
    #pragma unroll
    for (int o = 1; o < 32; o <<= 1) {
        int t = __shfl_up_sync(FULL, s, o);
        if (lane >= o) s += t;
    }
    if (lane == 31) wsum[w] = s;
    __syncthreads();
    if (w == 0) {
        int ws = wsum[lane];
        #pragma unroll
        for (int o = 1; o < 32; o <<= 1) {
            int t = __shfl_up_sync(FULL, ws, o);
            if (lane >= o) ws += t;
        }
        wsum[lane] = ws;
    }
    __syncthreads();
    int base = (w > 0) ? wsum[w - 1] : 0;
    if (i < n) g_off[i] = base + s - v;                     // exclusive
    if (threadIdx.x == SCAN_BLK - 1) g_bsum[blockIdx.x] = base + s;
}

// ---------------- scan 2+3 fused: add block prefix, place self-loops --------
__global__ void k_scan23(int n, int EE) {
    __shared__ int sbase;
    if (threadIdx.x < 32) {
        int q = blockIdx.x >> 2;        // owning scan1 block
        int val = 0;
        for (int j = (int)threadIdx.x; j < q; j += 32) val += g_bsum[j];
        #pragma unroll
        for (int o = 16; o >= 1; o >>= 1) val += __shfl_xor_sync(FULL, val, o);
        if (threadIdx.x == 0) sbase = val;
    }
    __syncthreads();
    if (blockIdx.x == 0 && threadIdx.x == 0) g_off[n] = EE;
    int i = blockIdx.x * 256 + threadIdx.x;
    if (i >= n) return;
    int o = g_off[i] + sbase;
    g_off[i]  = o;
    g_srcl[o] = i;                      // self loop at slot 0 of segment
}

// ---------------- scatter: atomic-free, 8 edges/thread, batched loads -------
__global__ void k_scatter(const int* __restrict__ ei, int E) {
    int t  = blockIdx.x * blockDim.x + threadIdx.x;
    int E8 = E >> 3;
    if (t < E8) {
        int4 s0 = ldcs4(((const int4*)ei) + 2 * t);
        int4 s1 = ldcs4(((const int4*)ei) + 2 * t + 1);
        int4 d0 = ldcs4(((const int4*)(ei + E)) + 2 * t);
        int4 d1 = ldcs4(((const int4*)(ei + E)) + 2 * t + 1);
        int4 r0 = ldcs4(((const int4*)g_rank) + 2 * t);
        int4 r1 = ldcs4(((const int4*)g_rank) + 2 * t + 1);
        // batch all 8 independent off-gathers before any dependent store
        int o0 = g_off[d0.x], o1 = g_off[d0.y], o2 = g_off[d0.z], o3 = g_off[d0.w];
        int o4 = g_off[d1.x], o5 = g_off[d1.y], o6 = g_off[d1.z], o7 = g_off[d1.w];
        g_srcl[o0 + 1 + r0.x] = s0.x;
        g_srcl[o1 + 1 + r0.y] = s0.y;
        g_srcl[o2 + 1 + r0.z] = s0.z;
        g_srcl[o3 + 1 + r0.w] = s0.w;
        g_srcl[o4 + 1 + r1.x] = s1.x;
        g_srcl[o5 + 1 + r1.y] = s1.y;
        g_srcl[o6 + 1 + r1.z] = s1.z;
        g_srcl[o7 + 1 + r1.w] = s1.w;
    } else if (t == E8) {
        for (int e = E8 * 8; e < E; e++)
            g_srcl[g_off[ei[E + e]] + 1 + g_rank[e]] = ei[e];
    }
}

// ---------------- layer1 aggregate: warp/dst, 1 lane/edge, linearity trick --
__global__ void k_agg1_csr(const float* __restrict__ x, const float* __restrict__ W1,
                           const float* __restrict__ b1, int n) {
    int warp = (blockIdx.x * blockDim.x + threadIdx.x) >> 5;
    if (warp >= n) return;
    int lane  = threadIdx.x & 31;
    int start = g_off[warp];
    int deg   = g_off[warp + 1] - start;
    float adv = g_ad[warp];
    float wa0 = g_w1a[0], wa1 = g_w1a[1];
    float psum = 0.f, px0 = 0.f, px1 = 0.f;
    for (int i = lane; i < deg; i += 32) {
        int src = g_srcl[start + i];
        float2 xv = ((const float2*)x)[src];
        float p = __expf(lrelu(xv.x * wa0 + xv.y * wa1 + adv));
        psum += p; px0 += p * xv.x; px1 += p * xv.y;
    }
    #pragma unroll
    for (int o = 16; o >= 1; o >>= 1) {       // post-loop: warp fully convergent
        psum += __shfl_xor_sync(FULL, psum, o);
        px0  += __shfl_xor_sync(FULL, px0,  o);
        px1  += __shfl_xor_sync(FULL, px1,  o);
    }
    if (lane < 16) {
        float sinv = 1.f / psum;
        float v = fmaxf((px0 * __ldg(W1 + lane) + px1 * __ldg(W1 + 16 + lane)) * sinv
                        + __ldg(b1 + lane), 0.f);
        g_out1[warp * 16 + lane] = v;
        float pd = v * g_w2a[16 + lane];      // alpha_dst for layer 2
        #pragma unroll
        for (int o = 8; o >= 1; o >>= 1)
            pd += __shfl_xor_sync(0xffffu, pd, o);
        if (lane == 0) g_ad[warp] = pd;
    }
}

// ---------------- layer2 aggregate: warp/dst, 4 lanes/edge, pipelined -------
__global__ void k_agg2_csr(const float* __restrict__ W2, const float* __restrict__ b2,
                           float* __restrict__ out, int n) {
    __shared__ float sW[1024];   // W2 16x64
    for (int i = threadIdx.x; i < 1024; i += blockDim.x) sW[i] = W2[i];
    __syncthreads();

    int warp = (blockIdx.x * blockDim.x + threadIdx.x) >> 5;
    if (warp >= n) return;
    int lane = threadIdx.x & 31;
    int fl   = lane & 3;             // feature slice (4 floats)
    int sub  = lane >> 2;            // 8 edges in parallel
    int start = g_off[warp];
    int deg   = g_off[warp + 1] - start;
    float adv = g_ad[warp];
    float wsa = g_w2a[fl * 4 + 0], wsb = g_w2a[fl * 4 + 1];
    float wsc = g_w2a[fl * 4 + 2], wsd = g_w2a[fl * 4 + 3];

    float4 acc = make_float4(0.f, 0.f, 0.f, 0.f);
    float psum = 0.f;
    int iters = (deg + 7) >> 3;                // warp-uniform trip count

    bool  v0 = (sub < deg);
    int   s0 = v0 ? g_srcl[start + sub] : 0;
    float4 hv0 = v0 ? *(const float4*)(g_out1 + s0 * 16 + fl * 4)
                    : make_float4(0.f, 0.f, 0.f, 0.f);

    for (int it = 0; it < iters; it++) {
        int i1 = (it + 1) * 8 + sub;
        bool v1 = (i1 < deg);
        int  s1 = v1 ? g_srcl[start + i1] : 0;
        float4 hv1 = v1 ? *(const float4*)(g_out1 + s1 * 16 + fl * 4)
                        : make_float4(0.f, 0.f, 0.f, 0.f);

        float pa = hv0.x * wsa + hv0.y * wsb + hv0.z * wsc + hv0.w * wsd;
        pa += __shfl_xor_sync(FULL, pa, 1);
        pa += __shfl_xor_sync(FULL, pa, 2);    // alpha_src, same in all 4 lanes
        float p = v0 ? __expf(lrelu(pa + adv)) : 0.f;
        psum += p;
        acc.x += p * hv0.x; acc.y += p * hv0.y;
        acc.z += p * hv0.z; acc.w += p * hv0.w;

        hv0 = hv1; v0 = v1;
    }
    #pragma unroll
    for (int o = 4; o <= 16; o <<= 1) {        // reduce across the 8 subgroups
        acc.x += __shfl_xor_sync(FULL, acc.x, o);
        acc.y += __shfl_xor_sync(FULL, acc.y, o);
        acc.z += __shfl_xor_sync(FULL, acc.z, o);
        acc.w += __shfl_xor_sync(FULL, acc.w, o);
        psum  += __shfl_xor_sync(FULL, psum,  o);
    }
    float sinv = 1.f / psum;
    float t[16];
    #pragma unroll
    for (int k = 0; k < 16; k++) {
        float c = ((k & 3) == 0) ? acc.x : ((k & 3) == 1) ? acc.y
                 : ((k & 3) == 2) ? acc.z : acc.w;
        t[k] = __shfl_sync(FULL, c, k >> 2) * sinv;   // lane (k>>2) has fl==k>>2
    }
    float2 r = make_float2(0.f, 0.f);
    #pragma unroll
    for (int k = 0; k < 16; k++) {
        float2 w = *(const float2*)&sW[k * 64 + 2 * lane];
        r.x += t[k] * w.x;
        r.y += t[k] * w.y;
    }
    float2 bb = __ldg((const float2*)b2 + lane);
    r.x = fmaxf(r.x + bb.x, 0.f);
    r.y = fmaxf(r.y + bb.y, 0.f);
    ((float2*)(out + warp * 64))[lane] = r;
}

// ---------------- launch -----------------------------------------------------
extern "C" void kernel_launch(void* const* d_in, const int* in_sizes, int n_in,
                              void* d_out, int out_size) {
    const float* x   = (const float*)d_in[0];
    const int*   ei  = (const int*)  d_in[1];
    const float* W1  = (const float*)d_in[2];
    const float* as1 = (const float*)d_in[3];
    const float* ad1 = (const float*)d_in[4];
    const float* b1  = (const float*)d_in[5];
    const float* W2  = (const float*)d_in[6];
    const float* as2 = (const float*)d_in[7];
    const float* ad2 = (const float*)d_in[8];
    const float* b2  = (const float*)d_in[9];
    float* out = (float*)d_out;

    int n  = in_sizes[0] / 2;   // 100000
    int E  = in_sizes[1] / 2;   // 3.2M
    int EE = E + n;

    const int T = 256;
    int E8c  = (E >> 3) + 1;                     // 8-edge threads (+tail thread)
    int hthr = E8c > n ? E8c : n;                // hist + node-init threads

    k_hist_init<<<(hthr + T - 1) / T, T>>>(ei, x, W1, as1, ad1, W2, as2, ad2, E, n);
    k_scan1<<<(n + SCAN_BLK - 1) / SCAN_BLK, SCAN_BLK>>>(n);
    k_scan23<<<(n + 255) / 256, 256>>>(n, EE);
    k_scatter<<<(E8c + T - 1) / T, T>>>(ei, E);
    k_agg1_csr<<<(n * 32 + T - 1) / T, T>>>(x, W1, b1, n);
    k_agg2_csr<<<(n * 32 + T - 1) / T, T>>>(W2, b2, out, n);
}